// round 5
// baseline (speedup 1.0000x reference)
#include <cuda_runtime.h>
#include <cstdint>

// Problem constants
#define Bn 8
#define Tn 256
#define Un 64
#define Hn 512
#define Fn 1024

// tf32-prerounded copies (no cudaMalloc allowed -> device globals)
__device__ float g_audio[Bn * Tn * Hn];   // 4 MB
__device__ float g_label[Bn * Un * Hn];   // 1 MB
__device__ float g_w[2 * Hn * Fn];        // 4 MB

__device__ __forceinline__ float to_tf32(float x) {
    float r;
    asm("cvt.rna.tf32.f32 %0, %1;" : "=f"(r) : "f"(x));
    return r;
}

// ---------------------------------------------------------------------------
// Prep: round all GEMM operands to tf32 (RNA) once. Lets the main kernel use
// cp.async with zero in-register conversion, with RNA accuracy preserved.
// ---------------------------------------------------------------------------
__global__ __launch_bounds__(256)
void prep_kernel(const float* __restrict__ audio,
                 const float* __restrict__ label,
                 const float* __restrict__ W)
{
    const int NA = Bn * Tn * Hn / 4;   // 262144 float4
    const int NL = Bn * Un * Hn / 4;   // 65536
    int i = blockIdx.x * 256 + threadIdx.x;
    const float4* src;
    float4* dst;
    if (i < NA)           { src = (const float4*)audio + i;            dst = (float4*)g_audio + i; }
    else if (i < NA + NL) { src = (const float4*)label + (i - NA);     dst = (float4*)g_label + (i - NA); }
    else                  { src = (const float4*)W + (i - NA - NL);    dst = (float4*)g_w + (i - NA - NL); }
    float4 v = *src;
    float4 o = { to_tf32(v.x), to_tf32(v.y), to_tf32(v.z), to_tf32(v.w) };
    *dst = o;
}

// ---------------------------------------------------------------------------
// Fused kernel. CTA = (b, 64 t-rows, 256 f-cols).
// GEMM: 128 M-rows (rows 0..63 audio t, rows 64..127 label u) x 256 N x 512 K.
//   Warps 0-7 : audio rows with Wa tile.   Warps 8-15: label rows with Wl tile.
//   Per role: 2(M) x 4(N) warps, warp tile 32x64, m16n8k8 tf32 mma.
//   2-stage cp.async pipeline, BK=32 (16 iters).
// Epilogue: stage C (128 x 256, pitch 260) in SMEM (union with GEMM buffers),
//   then stream out[t,u,f] = Ca[t,f] + Cl[u,f] with .cs float4 stores.
// ---------------------------------------------------------------------------
#define STG_FL 21248      // stage size in floats (84992 B)
#define OFF_L  2304       // float offsets within a stage
#define OFF_BA 4608
#define OFF_BL 12928
#define SMEM_BYTES 169984 // 2 stages; C tile (133120 B) unions into this

extern __shared__ float smem[];

#define CPA16(dst, src) \
    asm volatile("cp.async.cg.shared.global [%0], [%1], 16;" :: "r"(dst), "l"(src))

__global__ __launch_bounds__(512)
void joint_fused(const float* __restrict__ bias, float* __restrict__ out)
{
    const int fb = blockIdx.x;            // 0..3   (f tile of 256)
    const int rb = blockIdx.y;            // 0..31
    const int b  = rb >> 2;
    const int t0 = (rb & 3) << 6;

    const int tid  = threadIdx.x;
    const int warp = tid >> 5;
    const int lane = tid & 31;
    const int role = warp >> 3;           // 0 = audio, 1 = label
    const int w8   = warp & 7;
    const int wm   = w8 >> 2;             // 0..1
    const int wn   = w8 & 3;              // 0..3
    const int g    = lane >> 2;           // 0..7
    const int tig  = lane & 3;            // 0..3

    const uint32_t sb = (uint32_t)__cvta_generic_to_shared(smem);

    // ---- cp.async source/dest coordinates (per thread) ----
    const int rA = tid >> 3;              // 0..63
    const int cA = tid & 7;               // float4 index along K (BK=32)
    const float* a_src = g_audio + (size_t)(b * Tn + t0 + rA) * Hn + cA * 4;
    const float* l_src = g_label + (size_t)(b * Un + rA) * Hn + cA * 4;
    const uint32_t dA = (uint32_t)(rA * 36 + cA * 4) * 4;
    const uint32_t dL = 9216u + dA;

    const float* wa_src[4];
    const float* wl_src[4];
    uint32_t dWa[4], dWl[4];
#pragma unroll
    for (int i = 0; i < 4; i++) {
        int id = tid + i * 512;
        int kr = id >> 6;                 // 0..31
        int cw = id & 63;                 // float4 index along N (256)
        wa_src[i] = g_w + (size_t)kr * Fn + fb * 256 + cw * 4;
        wl_src[i] = g_w + (size_t)(Hn + kr) * Fn + fb * 256 + cw * 4;
        dWa[i] = 18432u + (uint32_t)(kr * 260 + cw * 4) * 4;
        dWl[i] = 51712u + (uint32_t)(kr * 260 + cw * 4) * 4;
    }

    float c[2][8][4];
#pragma unroll
    for (int mt = 0; mt < 2; mt++)
#pragma unroll
        for (int nt = 0; nt < 8; nt++)
#pragma unroll
            for (int r = 0; r < 4; r++) c[mt][nt][r] = 0.0f;

    // Stage issue: loads one BK=32 tile set into stage s, advances pointers.
    auto issue = [&](int s) {
        const uint32_t st = sb + (uint32_t)s * 84992u;
        CPA16(st + dA, a_src);
        CPA16(st + dL, l_src);
#pragma unroll
        for (int i = 0; i < 4; i++) {
            CPA16(st + dWa[i], wa_src[i]);
            CPA16(st + dWl[i], wl_src[i]);
        }
        asm volatile("cp.async.commit_group;");
        a_src += 32; l_src += 32;
#pragma unroll
        for (int i = 0; i < 4; i++) { wa_src[i] += 32 * Fn; wl_src[i] += 32 * Fn; }
    };

    issue(0);

#pragma unroll 1
    for (int it = 0; it < 16; ++it) {
        const int s = it & 1;
        if (it < 15) {
            issue(s ^ 1);
            asm volatile("cp.async.wait_group 1;");
        } else {
            asm volatile("cp.async.wait_group 0;");
        }
        __syncthreads();                   // stage s visible to all threads

        const float* at = smem + s * STG_FL + role * OFF_L;
        const float* bt = smem + s * STG_FL + OFF_BA + role * (OFF_BL - OFF_BA);

#pragma unroll
        for (int ks = 0; ks < 4; ks++) {
            const int k0 = ks * 8 + tig;
            uint32_t af[2][4];
#pragma unroll
            for (int mt = 0; mt < 2; mt++) {
                int r0 = wm * 32 + mt * 16 + g;
                af[mt][0] = __float_as_uint(at[r0 * 36 + k0]);
                af[mt][1] = __float_as_uint(at[(r0 + 8) * 36 + k0]);
                af[mt][2] = __float_as_uint(at[r0 * 36 + k0 + 4]);
                af[mt][3] = __float_as_uint(at[(r0 + 8) * 36 + k0 + 4]);
            }
            uint32_t bf[8][2];
#pragma unroll
            for (int nt = 0; nt < 8; nt++) {
                int n0 = wn * 64 + nt * 8 + g;
                bf[nt][0] = __float_as_uint(bt[k0 * 260 + n0]);
                bf[nt][1] = __float_as_uint(bt[(k0 + 4) * 260 + n0]);
            }
#pragma unroll
            for (int mt = 0; mt < 2; mt++)
#pragma unroll
                for (int nt = 0; nt < 8; nt++) {
                    asm volatile(
                        "mma.sync.aligned.m16n8k8.row.col.f32.tf32.tf32.f32 "
                        "{%0,%1,%2,%3}, {%4,%5,%6,%7}, {%8,%9}, {%0,%1,%2,%3};"
                        : "+f"(c[mt][nt][0]), "+f"(c[mt][nt][1]),
                          "+f"(c[mt][nt][2]), "+f"(c[mt][nt][3])
                        : "r"(af[mt][0]), "r"(af[mt][1]),
                          "r"(af[mt][2]), "r"(af[mt][3]),
                          "r"(bf[nt][0]), "r"(bf[nt][1]));
                }
        }
        __syncthreads();                   // reads done before next overwrite
    }

    // ---- Stage C into SMEM (union over GEMM buffers), bias on audio half ----
    float* Cs = smem;                       // 128 rows x 256 f, pitch 260
    const int crow = role * 64 + wm * 32;
#pragma unroll
    for (int nt = 0; nt < 8; nt++) {
        const int col = wn * 64 + nt * 8 + 2 * tig;
        float b0 = 0.0f, b1 = 0.0f;
        if (role == 0) {
            b0 = bias[fb * 256 + col];
            b1 = bias[fb * 256 + col + 1];
        }
#pragma unroll
        for (int mt = 0; mt < 2; mt++) {
            const int row = crow + mt * 16 + g;
            float2 v0 = { c[mt][nt][0] + b0, c[mt][nt][1] + b1 };
            float2 v1 = { c[mt][nt][2] + b0, c[mt][nt][3] + b1 };
            *(float2*)&Cs[row * 260 + col]       = v0;
            *(float2*)&Cs[(row + 8) * 260 + col] = v1;
        }
    }
    __syncthreads();

    // ---- Broadcast store: out[b, t0+t, u, fb*256 + f] = Ca[t][f] + Cl[u][f] ----
    const float4* Cs4 = (const float4*)smem;     // row pitch 65 float4
    float4* out4 = (float4*)out;
    const size_t obase = ((size_t)(b * Tn + t0) * Un) * (Fn / 4) + fb * 64 + lane;

#pragma unroll 2
    for (int tt = 0; tt < 64; ++tt) {
        const float4 a0 = Cs4[tt * 65 + lane];
        const float4 a1 = Cs4[tt * 65 + lane + 32];
        const size_t rowbase = obase + (size_t)tt * Un * (Fn / 4);
#pragma unroll
        for (int uu = 0; uu < 4; ++uu) {
            const int u = uu * 16 + warp;
            const float4 l0 = Cs4[(64 + u) * 65 + lane];
            const float4 l1 = Cs4[(64 + u) * 65 + lane + 32];
            float4 v0 = { a0.x + l0.x, a0.y + l0.y, a0.z + l0.z, a0.w + l0.w };
            float4 v1 = { a1.x + l1.x, a1.y + l1.y, a1.z + l1.z, a1.w + l1.w };
            const size_t addr = rowbase + (size_t)u * (Fn / 4);
            __stcs(out4 + addr, v0);
            __stcs(out4 + addr + 32, v1);
        }
    }
}

// ---------------------------------------------------------------------------
extern "C" void kernel_launch(void* const* d_in, const int* in_sizes, int n_in,
                              void* d_out, int out_size)
{
    const float* audio = (const float*)d_in[0];   // (8,256,512)
    const float* label = (const float*)d_in[1];   // (8,64,512)
    const float* W     = (const float*)d_in[2];   // (1024,1024)
    const float* bias  = (const float*)d_in[3];   // (1024,)
    float* out = (float*)d_out;                   // (8,256,64,1024)

    cudaFuncSetAttribute(joint_fused,
                         cudaFuncAttributeMaxDynamicSharedMemorySize, SMEM_BYTES);

    prep_kernel<<<2304, 256>>>(audio, label, W);
    joint_fused<<<dim3(4, 32), 512, SMEM_BYTES>>>(bias, out);
}

// round 6
// speedup vs baseline: 1.0993x; 1.0993x over previous
#include <cuda_runtime.h>
#include <cstdint>

// Problem constants
#define Bn 8
#define Tn 256
#define Un 64
#define Hn 512
#define Fn 1024

// tf32-prerounded copies (no cudaMalloc allowed -> device globals)
__device__ float g_audio[Bn * Tn * Hn];   // 4 MB
__device__ float g_label[Bn * Un * Hn];   // 1 MB
__device__ float g_w[2 * Hn * Fn];        // 4 MB

__device__ __forceinline__ float to_tf32(float x) {
    float r;
    asm("cvt.rna.tf32.f32 %0, %1;" : "=f"(r) : "f"(x));
    return r;
}

// ---------------------------------------------------------------------------
// Prep: round all GEMM operands to tf32 (RNA) once.
// ---------------------------------------------------------------------------
__global__ __launch_bounds__(256)
void prep_kernel(const float* __restrict__ audio,
                 const float* __restrict__ label,
                 const float* __restrict__ W)
{
    const int NA = Bn * Tn * Hn / 4;   // 262144 float4
    const int NL = Bn * Un * Hn / 4;   // 65536
    int i = blockIdx.x * 256 + threadIdx.x;
    const float4* src;
    float4* dst;
    if (i < NA)           { src = (const float4*)audio + i;            dst = (float4*)g_audio + i; }
    else if (i < NA + NL) { src = (const float4*)label + (i - NA);     dst = (float4*)g_label + (i - NA); }
    else                  { src = (const float4*)W + (i - NA - NL);    dst = (float4*)g_w + (i - NA - NL); }
    float4 v = *src;
    float4 o = { to_tf32(v.x), to_tf32(v.y), to_tf32(v.z), to_tf32(v.w) };
    *dst = o;
}

// ---------------------------------------------------------------------------
// Fused kernel. CTA = (b, 64 t-rows, 32 f-cols). 1024 CTAs, 4/SM.
// GEMM: M=128 (rows 0..63 audio t, 64..127 label u), N=32, K=512, BK=32.
//   Warps 0-3 audio (Wa), warps 4-7 label (Wl); per role 2(M)x2(N) warps,
//   warp tile 32x16, tf32 m16n8k8. 2-stage cp.async pipeline.
// Epilogue: stage C (128 x 32, pitch 40) in SMEM (union with GEMM stages),
//   then stream out[t,u,f] = Ca[t,f] + Cl[u,f] (+bias) with .cs stores.
// SMEM stage layout (floats): AL 128x36 @0, Wa 32x40 @4608, Wl 32x40 @5888.
// Stage = 7168 floats (28672 B); 2 stages = 57344 B. C tile (5120 fl) unions.
// ---------------------------------------------------------------------------
#define STG_FL 7168
#define SMEM_BYTES 57344

extern __shared__ float smem[];

#define CPA16(dst, src) \
    asm volatile("cp.async.cg.shared.global [%0], [%1], 16;" :: "r"(dst), "l"(src))

__global__ __launch_bounds__(256, 4)
void joint_fused(const float* __restrict__ bias, float* __restrict__ out)
{
    const int fb = blockIdx.x;            // 0..31  (f tile of 32)
    const int tb = blockIdx.y;            // 0..3   (t tile of 64)
    const int b  = blockIdx.z;            // 0..7

    const int tid  = threadIdx.x;
    const int warp = tid >> 5;
    const int lane = tid & 31;
    const int role = warp >> 2;           // 0 = audio, 1 = label
    const int w4   = warp & 3;
    const int wm   = w4 >> 1;             // 0..1 (M)
    const int wn_  = w4 & 1;              // 0..1 (N)
    const int g    = lane >> 2;           // 0..7
    const int tig  = lane & 3;            // 0..3

    const uint32_t sb = (uint32_t)__cvta_generic_to_shared(smem);

    // ---- cp.async coordinates ----
    // A/L: 64 rows x 8 float4 = 512 float4 each -> 2 per thread.
    int rA[2], cA[2];
    const float* a_src[2];
    const float* l_src[2];
    uint32_t dA[2];
#pragma unroll
    for (int i = 0; i < 2; i++) {
        int id = tid + i * 256;
        rA[i] = id >> 3;  cA[i] = id & 7;
        a_src[i] = g_audio + (size_t)(b * Tn + tb * 64 + rA[i]) * Hn + cA[i] * 4;
        l_src[i] = g_label + (size_t)(b * Un + rA[i]) * Hn + cA[i] * 4;
        dA[i] = (uint32_t)(rA[i] * 36 + cA[i] * 4) * 4;
    }
    // W: 32 K x 8 float4 = 256 float4 per half -> 1 per thread.
    const int kr = tid >> 3;
    const int cw = tid & 7;
    const float* wa_src = g_w + (size_t)kr * Fn + fb * 32 + cw * 4;
    const float* wl_src = g_w + (size_t)(Hn + kr) * Fn + fb * 32 + cw * 4;
    const uint32_t dWa = (uint32_t)(4608 + kr * 40 + cw * 4) * 4;
    const uint32_t dWl = dWa + 1280u * 4;

    float c[2][2][4];
#pragma unroll
    for (int mt = 0; mt < 2; mt++)
#pragma unroll
        for (int nt = 0; nt < 2; nt++)
#pragma unroll
            for (int r = 0; r < 4; r++) c[mt][nt][r] = 0.0f;

    auto issue = [&](int s) {
        const uint32_t st = sb + (uint32_t)s * (STG_FL * 4);
#pragma unroll
        for (int i = 0; i < 2; i++) {
            CPA16(st + dA[i], a_src[i]);
            CPA16(st + dA[i] + 9216u, l_src[i]);   // label rows 64..127
        }
        CPA16(st + dWa, wa_src);
        CPA16(st + dWl, wl_src);
        asm volatile("cp.async.commit_group;");
#pragma unroll
        for (int i = 0; i < 2; i++) { a_src[i] += 32; l_src[i] += 32; }
        wa_src += 32 * Fn;  wl_src += 32 * Fn;
    };

    issue(0);

#pragma unroll 1
    for (int it = 0; it < 16; ++it) {
        const int s = it & 1;
        if (it < 15) {
            issue(s ^ 1);
            asm volatile("cp.async.wait_group 1;");
        } else {
            asm volatile("cp.async.wait_group 0;");
        }
        __syncthreads();

        const float* at = smem + s * STG_FL;                      // AL 128x36
        const float* wt = smem + s * STG_FL + 4608 + role * 1280; // W half 32x40

#pragma unroll
        for (int ks = 0; ks < 4; ks++) {
            const int k0 = ks * 8 + tig;
            uint32_t af[2][4], bf[2][2];
#pragma unroll
            for (int mt = 0; mt < 2; mt++) {
                const int arow = role * 64 + wm * 32 + mt * 16 + g;
                af[mt][0] = __float_as_uint(at[arow * 36 + k0]);
                af[mt][1] = __float_as_uint(at[(arow + 8) * 36 + k0]);
                af[mt][2] = __float_as_uint(at[arow * 36 + k0 + 4]);
                af[mt][3] = __float_as_uint(at[(arow + 8) * 36 + k0 + 4]);
            }
#pragma unroll
            for (int nt = 0; nt < 2; nt++) {
                const int n0 = wn_ * 16 + nt * 8 + g;
                bf[nt][0] = __float_as_uint(wt[k0 * 40 + n0]);
                bf[nt][1] = __float_as_uint(wt[(k0 + 4) * 40 + n0]);
            }
#pragma unroll
            for (int mt = 0; mt < 2; mt++)
#pragma unroll
                for (int nt = 0; nt < 2; nt++) {
                    asm volatile(
                        "mma.sync.aligned.m16n8k8.row.col.f32.tf32.tf32.f32 "
                        "{%0,%1,%2,%3}, {%4,%5,%6,%7}, {%8,%9}, {%0,%1,%2,%3};"
                        : "+f"(c[mt][nt][0]), "+f"(c[mt][nt][1]),
                          "+f"(c[mt][nt][2]), "+f"(c[mt][nt][3])
                        : "r"(af[mt][0]), "r"(af[mt][1]),
                          "r"(af[mt][2]), "r"(af[mt][3]),
                          "r"(bf[nt][0]), "r"(bf[nt][1]));
                }
        }
        __syncthreads();
    }

    // ---- Stage C into SMEM: 128 rows x 32 f, pitch 40 floats ----
    float* Cs = smem;
#pragma unroll
    for (int nt = 0; nt < 2; nt++) {
        const int col = wn_ * 16 + nt * 8 + 2 * tig;
        float b0 = 0.0f, b1 = 0.0f;
        if (role == 0) {
            b0 = bias[fb * 32 + col];
            b1 = bias[fb * 32 + col + 1];
        }
#pragma unroll
        for (int mt = 0; mt < 2; mt++) {
            const int row = role * 64 + wm * 32 + mt * 16 + g;
            float2 v0 = { c[mt][nt][0] + b0, c[mt][nt][1] + b1 };
            float2 v1 = { c[mt][nt][2] + b0, c[mt][nt][3] + b1 };
            *(float2*)&Cs[row * 40 + col]       = v0;
            *(float2*)&Cs[(row + 8) * 40 + col] = v1;
        }
    }
    __syncthreads();

    // ---- Broadcast store ----
    // Per (t,u) row: 32 f = 8 float4. Warp covers 4 u-rows per step.
    // Warp w owns u in [w*8, w*8+8); lane: fi = lane&7, uh = lane>>3 (0..3).
    const float4* Cs4 = (const float4*)smem;   // pitch 10 float4
    float4* out4 = (float4*)out;
    const int fi = lane & 7;
    const int uh = lane >> 3;

    float4 lreg[2];
#pragma unroll
    for (int i = 0; i < 2; i++) {
        const int u = warp * 8 + i * 4 + uh;
        lreg[i] = Cs4[(64 + u) * 10 + fi];
    }

    const size_t row0 = ((size_t)(b * Tn + tb * 64) * Un) * (Fn / 4) + fb * 8 + fi;

#pragma unroll 2
    for (int tt = 0; tt < 64; ++tt) {
        const float4 a = Cs4[tt * 10 + fi];          // broadcast across uh
        const size_t tbase = row0 + (size_t)tt * Un * (Fn / 4);
#pragma unroll
        for (int i = 0; i < 2; i++) {
            const int u = warp * 8 + i * 4 + uh;
            float4 v = { a.x + lreg[i].x, a.y + lreg[i].y,
                         a.z + lreg[i].z, a.w + lreg[i].w };
            __stcs(out4 + tbase + (size_t)u * (Fn / 4), v);
        }
    }
}

// ---------------------------------------------------------------------------
extern "C" void kernel_launch(void* const* d_in, const int* in_sizes, int n_in,
                              void* d_out, int out_size)
{
    const float* audio = (const float*)d_in[0];   // (8,256,512)
    const float* label = (const float*)d_in[1];   // (8,64,512)
    const float* W     = (const float*)d_in[2];   // (1024,1024)
    const float* bias  = (const float*)d_in[3];   // (1024,)
    float* out = (float*)d_out;                   // (8,256,64,1024)

    cudaFuncSetAttribute(joint_fused,
                         cudaFuncAttributeMaxDynamicSharedMemorySize, SMEM_BYTES);

    prep_kernel<<<2304, 256>>>(audio, label, W);
    joint_fused<<<dim3(32, 4, 8), 256, SMEM_BYTES>>>(bias, out);
}